// round 6
// baseline (speedup 1.0000x reference)
#include <cuda_runtime.h>
#include <stdint.h>

// Problem constants (match reference setup)
#define NN 100000
#define NE 1600000
#define SCAN_B 1024
#define NB ((NN + SCAN_B - 1) / SCAN_B)   // 98

// ---------------- scratch (device globals, ~59 MB total) -------------------
__device__ int   g_is64;
__device__ int   g_cnt[NN];
__device__ int   g_rptr[NN + 1];
__device__ int   g_woff[NN];
__device__ int   g_bsum[NB];
__device__ int   g_col[NE];
__device__ __align__(16) float g_h[NN * 128];      // layer-1 output (51.2 MB)
__device__ __align__(16) float g_B1[256 * 128];    // [Wl0 ; Wr0]
__device__ __align__(16) float g_B2[256 * 64];     // [Wl1 ; Wr1]

// ---------------- edge_index dtype detection -------------------------------
// int64 node ids < 2^31 have zero high words at odd int32 indices; int32
// random node ids in [0,100000) cannot have 1024 consecutive odd words all 0.
__global__ void k_detect(const int* __restrict__ ei32) {
    __shared__ int nz;
    if (threadIdx.x == 0) nz = 0;
    __syncthreads();
    int v = 0;
    for (int i = threadIdx.x; i < 1024; i += 256) v |= ei32[2 * i + 1];
    if (v) atomicOr(&nz, 1);
    __syncthreads();
    if (threadIdx.x == 0) g_is64 = (nz == 0) ? 1 : 0;
}

__device__ __forceinline__ int edge_at(const void* ei, int idx) {
    return g_is64 ? (int)((const long long*)ei)[idx] : ((const int*)ei)[idx];
}

// ---------------- CSR build ----------------
__global__ void k_zero_cnt(int n) {
    int i = blockIdx.x * blockDim.x + threadIdx.x;
    if (i < n) g_cnt[i] = 0;
}

__global__ void k_hist(const void* __restrict__ ei, int E) {
    int e = blockIdx.x * blockDim.x + threadIdx.x;
    if (e < E) {
        int d = edge_at(ei, E + e);
        if ((unsigned)d < (unsigned)NN) atomicAdd(&g_cnt[d], 1);
    }
}

__global__ void k_scan_blocks(int n) {
    __shared__ int wsum[32];
    int tid  = threadIdx.x;
    int lane = tid & 31, wid = tid >> 5;
    int i = blockIdx.x * SCAN_B + tid;
    int v = (i < n) ? g_cnt[i] : 0;
    int x = v;
    #pragma unroll
    for (int d = 1; d < 32; d <<= 1) {
        int t = __shfl_up_sync(0xffffffffu, x, d);
        if (lane >= d) x += t;
    }
    if (lane == 31) wsum[wid] = x;
    __syncthreads();
    if (wid == 0) {
        int s = wsum[lane];
        #pragma unroll
        for (int d = 1; d < 32; d <<= 1) {
            int t = __shfl_up_sync(0xffffffffu, s, d);
            if (lane >= d) s += t;
        }
        wsum[lane] = s;
    }
    __syncthreads();
    int woffs = (wid > 0) ? wsum[wid - 1] : 0;
    if (i < n) g_rptr[i] = woffs + x - v;
    if (tid == SCAN_B - 1) g_bsum[blockIdx.x] = wsum[31];
}

__global__ void k_scan_bsum(int nb) {
    __shared__ int s[NB];
    int tid = threadIdx.x;
    if (tid < nb) s[tid] = g_bsum[tid];
    __syncthreads();
    if (tid == 0) {
        int acc = 0;
        for (int i = 0; i < nb; i++) { int t = s[i]; s[i] = acc; acc += t; }
    }
    __syncthreads();
    if (tid < nb) g_bsum[tid] = s[tid];
}

__global__ void k_add_off(int n, int E) {
    int i = blockIdx.x * SCAN_B + threadIdx.x;
    if (i < n) {
        int v = g_rptr[i] + g_bsum[blockIdx.x];
        g_rptr[i] = v;
        g_woff[i] = v;
    }
    if (i == 0) g_rptr[n] = E;
}

__global__ void k_scatter(const void* __restrict__ ei, int E) {
    int e = blockIdx.x * blockDim.x + threadIdx.x;
    if (e < E) {
        int s = edge_at(ei, e);
        int d = edge_at(ei, E + e);
        if ((unsigned)s < (unsigned)NN && (unsigned)d < (unsigned)NN) {
            int p = atomicAdd(&g_woff[d], 1);
            if ((unsigned)p < (unsigned)NE) g_col[p] = s;
        }
    }
}

// ---------------- weight packing (contiguous copies) -----------------------
__global__ void k_pack(const float* __restrict__ Wl0, const float* __restrict__ Wr0,
                       const float* __restrict__ Wl1, const float* __restrict__ Wr1) {
    int i = blockIdx.x * blockDim.x + threadIdx.x;
    if (i < 128 * 128) {
        g_B1[i]             = Wl0[i];
        g_B1[128 * 128 + i] = Wr0[i];
    }
    if (i < 128 * 64) {
        g_B2[i]            = Wl1[i];
        g_B2[128 * 64 + i] = Wr1[i];
    }
}

// ---------------- fused SAGE layer: gather-mean + GEMM ---------------------
// Per block: 64-node tile.
//   Phase A: warp-per-node gather: Agg[r][0:128] = mean over neighbors of S[src]
//   Phase B: C = [Agg | S_rows] (K=256) @ B (+bias) -> relu (layer 0) -> out
// LAYER 0: S = x,   B = g_B1 (N=128), out = g_h, relu
// LAYER 1: S = g_h, B = g_B2 (N=64),  out = d_out, no relu
template <int LAYER>
__global__ void __launch_bounds__(256) k_fused(
    const float* __restrict__ srcext,   // LAYER 0: x; LAYER 1: unused
    const float* __restrict__ bias,
    float* __restrict__ outp,           // LAYER 1: d_out; LAYER 0: unused
    int M)
{
    constexpr int N  = (LAYER == 0) ? 128 : 64;
    constexpr int MR = (LAYER == 0) ? 8 : 4;

    // 132-float row stride: 528 B, 16B-divisible -> float4 on Agg stays aligned
    __shared__ float Agg[64][132];
    __shared__ float Bs[16][N];
    __shared__ float As2[64][20];

    const float* S  = (LAYER == 0) ? srcext : g_h;
    const float* Bw = (LAYER == 0) ? g_B1 : g_B2;

    int tid  = threadIdx.x;
    int lane = tid & 31, w = tid >> 5;
    int tile0 = blockIdx.x * 64;

    // -------- Phase A: gather-mean into Agg --------
    #pragma unroll 1
    for (int u = 0; u < 8; u++) {
        int r = w * 8 + u;
        int node = tile0 + r;
        float4 acc = make_float4(0.f, 0.f, 0.f, 0.f);
        if (node < M) {
            int rs = g_rptr[node], re = g_rptr[node + 1];
            int j = rs;
            for (; j + 4 <= re; j += 4) {
                int s0 = g_col[j], s1 = g_col[j+1], s2 = g_col[j+2], s3 = g_col[j+3];
                float4 v0 = *(const float4*)&S[s0 * 128 + lane * 4];
                float4 v1 = *(const float4*)&S[s1 * 128 + lane * 4];
                float4 v2 = *(const float4*)&S[s2 * 128 + lane * 4];
                float4 v3 = *(const float4*)&S[s3 * 128 + lane * 4];
                acc.x += v0.x + v1.x + v2.x + v3.x;
                acc.y += v0.y + v1.y + v2.y + v3.y;
                acc.z += v0.z + v1.z + v2.z + v3.z;
                acc.w += v0.w + v1.w + v2.w + v3.w;
            }
            for (; j < re; j++) {
                int s = g_col[j];
                float4 v = *(const float4*)&S[s * 128 + lane * 4];
                acc.x += v.x; acc.y += v.y; acc.z += v.z; acc.w += v.w;
            }
            int deg = re - rs;
            float inv = 1.0f / (float)(deg > 1 ? deg : 1);
            acc.x *= inv; acc.y *= inv; acc.z *= inv; acc.w *= inv;
        }
        *(float4*)&Agg[r][lane * 4] = acc;
    }

    // -------- Phase B: GEMM --------
    int tc = tid % (N / 4);
    int tr = tid / (N / 4);
    int n0 = tc * 4;
    int m0 = tr * MR;

    float acc[MR][4];
    #pragma unroll
    for (int i = 0; i < MR; i++)
        #pragma unroll
        for (int c = 0; c < 4; c++) acc[i][c] = 0.f;

    // K-half 1: A = Agg (already in shared)
    for (int kt = 0; kt < 128; kt += 16) {
        __syncthreads();   // Agg ready (1st iter); Bs consumed (later iters)
        #pragma unroll
        for (int u = 0; u < N / 64; u++) {
            int idx = tid + u * 256;
            int kr = idx / (N / 4), c4 = idx % (N / 4);
            *(float4*)&Bs[kr][c4 * 4] = *(const float4*)&Bw[(kt + kr) * N + c4 * 4];
        }
        __syncthreads();
        #pragma unroll
        for (int k = 0; k < 16; k++) {
            float a[MR];
            #pragma unroll
            for (int i = 0; i < MR; i++) a[i] = Agg[m0 + i][kt + k];
            float4 bq = *(float4*)&Bs[k][n0];
            #pragma unroll
            for (int i = 0; i < MR; i++) {
                acc[i][0] += a[i] * bq.x;
                acc[i][1] += a[i] * bq.y;
                acc[i][2] += a[i] * bq.z;
                acc[i][3] += a[i] * bq.w;
            }
        }
    }

    // K-half 2: A = own rows of S (staged through As2)
    for (int kt = 128; kt < 256; kt += 16) {
        __syncthreads();
        #pragma unroll
        for (int u = 0; u < N / 64; u++) {
            int idx = tid + u * 256;
            int kr = idx / (N / 4), c4 = idx % (N / 4);
            *(float4*)&Bs[kr][c4 * 4] = *(const float4*)&Bw[(kt + kr) * N + c4 * 4];
        }
        {
            int row = tid >> 2, c4 = tid & 3;
            int gr = tile0 + row;
            float4 v = make_float4(0.f, 0.f, 0.f, 0.f);
            if (gr < M) v = *(const float4*)&S[gr * 128 + (kt - 128) + c4 * 4];
            *(float4*)&As2[row][c4 * 4] = v;
        }
        __syncthreads();
        #pragma unroll
        for (int k = 0; k < 16; k++) {
            float a[MR];
            #pragma unroll
            for (int i = 0; i < MR; i++) a[i] = As2[m0 + i][k];
            float4 bq = *(float4*)&Bs[k][n0];
            #pragma unroll
            for (int i = 0; i < MR; i++) {
                acc[i][0] += a[i] * bq.x;
                acc[i][1] += a[i] * bq.y;
                acc[i][2] += a[i] * bq.z;
                acc[i][3] += a[i] * bq.w;
            }
        }
    }

    // -------- epilogue --------
    float b0 = bias[n0], b1 = bias[n0 + 1], b2 = bias[n0 + 2], b3 = bias[n0 + 3];
    #pragma unroll
    for (int i = 0; i < MR; i++) {
        int gm = tile0 + m0 + i;
        if (gm < M) {
            float4 o;
            o.x = acc[i][0] + b0;
            o.y = acc[i][1] + b1;
            o.z = acc[i][2] + b2;
            o.w = acc[i][3] + b3;
            if (LAYER == 0) {
                o.x = o.x > 0.f ? o.x : 0.f;
                o.y = o.y > 0.f ? o.y : 0.f;
                o.z = o.z > 0.f ? o.z : 0.f;
                o.w = o.w > 0.f ? o.w : 0.f;
                *(float4*)&g_h[gm * 128 + n0] = o;
            } else {
                *(float4*)&outp[gm * 64 + n0] = o;
            }
        }
    }
}

// ---------------- launch (kernel launches ONLY — no other CUDA API) --------
extern "C" void kernel_launch(void* const* d_in, const int* in_sizes, int n_in,
                              void* d_out, int out_size) {
    const float* x   = (const float*)d_in[0];
    const void*  ei  = d_in[1];                 // int32 or int64 — detected on device
    const float* Wl0 = (const float*)d_in[2];
    const float* bl0 = (const float*)d_in[3];
    const float* Wr0 = (const float*)d_in[4];
    const float* Wl1 = (const float*)d_in[5];
    const float* bl1 = (const float*)d_in[6];
    const float* Wr1 = (const float*)d_in[7];
    float* out = (float*)d_out;

    int M = in_sizes[0] / 128;      // 100000
    int E = in_sizes[1] / 2;        // 1600000 edges (2*E elements either dtype)

    // dtype probe + CSR build
    k_detect<<<1, 256>>>((const int*)ei);
    k_zero_cnt<<<(M + 255) / 256, 256>>>(M);
    k_hist<<<(E + 255) / 256, 256>>>(ei, E);
    k_scan_blocks<<<NB, SCAN_B>>>(M);
    k_scan_bsum<<<1, 128>>>(NB);
    k_add_off<<<NB, SCAN_B>>>(M, E);
    k_scatter<<<(E + 255) / 256, 256>>>(ei, E);
    k_pack<<<(128 * 128 + 255) / 256, 256>>>(Wl0, Wr0, Wl1, Wr1);

    int tiles = (M + 63) / 64;
    // layer 1: h = relu([mean-agg(x) | x] @ [Wl0;Wr0] + bl0)
    k_fused<0><<<tiles, 256>>>(x, bl0, nullptr, M);
    // layer 2: out = [mean-agg(h) | h] @ [Wl1;Wr1] + bl1
    k_fused<1><<<tiles, 256>>>(nullptr, bl1, out, M);
}

// round 7
// speedup vs baseline: 1.2422x; 1.2422x over previous
#include <cuda_runtime.h>
#include <cuda_bf16.h>
#include <stdint.h>

#define NN 100000
#define NE 1600000
#define SCAN_B 1024
#define NB ((NN + SCAN_B - 1) / SCAN_B)   // 98

// B1: 256x128 -> padded-packed u32 [256][68] (64 data + 4 pad)
// B2: 256x64  -> padded-packed u32 [256][36] (32 data + 4 pad)
#define B1U 68
#define B2U 36

// ---------------- scratch (device globals) ---------------------------------
__device__ int   g_is64;
__device__ int   g_cnt[NN];
__device__ int   g_rptr[NN + 1];
__device__ int   g_woff[NN];
__device__ int   g_bsum[NB];
__device__ int   g_col[NE];
__device__ __align__(16) float    g_h[NN * 128];
__device__ __align__(16) uint32_t g_B1h[256 * B1U];
__device__ __align__(16) uint32_t g_B1l[256 * B1U];
__device__ __align__(16) uint32_t g_B2h[256 * B2U];
__device__ __align__(16) uint32_t g_B2l[256 * B2U];

// ---------------- helpers --------------------------------------------------
__device__ __forceinline__ uint32_t sptr(const void* p) {
    uint32_t a;
    asm("{ .reg .u64 t; cvta.to.shared.u64 t, %1; cvt.u32.u64 %0, t; }"
        : "=r"(a) : "l"(p));
    return a;
}

#define LDSM_X4(r0,r1,r2,r3,addr) \
    asm volatile("ldmatrix.sync.aligned.m8n8.x4.shared.b16 {%0,%1,%2,%3}, [%4];" \
        : "=r"(r0),"=r"(r1),"=r"(r2),"=r"(r3) : "r"(addr))

#define LDSM_X4_T(r0,r1,r2,r3,addr) \
    asm volatile("ldmatrix.sync.aligned.m8n8.x4.trans.shared.b16 {%0,%1,%2,%3}, [%4];" \
        : "=r"(r0),"=r"(r1),"=r"(r2),"=r"(r3) : "r"(addr))

#define MMA16816(c, a0,a1,a2,a3, b0,b1) \
    asm volatile("mma.sync.aligned.m16n8k16.row.col.f32.bf16.bf16.f32 " \
        "{%0,%1,%2,%3},{%4,%5,%6,%7},{%8,%9},{%0,%1,%2,%3};" \
        : "+f"((c)[0]),"+f"((c)[1]),"+f"((c)[2]),"+f"((c)[3]) \
        : "r"(a0),"r"(a1),"r"(a2),"r"(a3),"r"(b0),"r"(b1))

// split f0,f1 (adjacent elems) into packed bf16 hi-pair and lo-pair u32s
__device__ __forceinline__ void split2(float f0, float f1, uint32_t& hi, uint32_t& lo) {
    __nv_bfloat162 h, l;
    h.x = __float2bfloat16(f0);
    h.y = __float2bfloat16(f1);
    l.x = __float2bfloat16(f0 - __bfloat162float(h.x));
    l.y = __float2bfloat16(f1 - __bfloat162float(h.y));
    hi = *reinterpret_cast<uint32_t*>(&h);
    lo = *reinterpret_cast<uint32_t*>(&l);
}

// ---------------- edge_index dtype detection -------------------------------
__global__ void k_detect(const int* __restrict__ ei32) {
    __shared__ int nz;
    if (threadIdx.x == 0) nz = 0;
    __syncthreads();
    int v = 0;
    for (int i = threadIdx.x; i < 1024; i += 256) v |= ei32[2 * i + 1];
    if (v) atomicOr(&nz, 1);
    __syncthreads();
    if (threadIdx.x == 0) g_is64 = (nz == 0) ? 1 : 0;
}

__device__ __forceinline__ int edge_at(const void* ei, int idx) {
    return g_is64 ? (int)((const long long*)ei)[idx] : ((const int*)ei)[idx];
}

// ---------------- CSR build ----------------
__global__ void k_zero_cnt(int n) {
    int i = blockIdx.x * blockDim.x + threadIdx.x;
    if (i < n) g_cnt[i] = 0;
}

__global__ void k_hist(const void* __restrict__ ei, int E) {
    int e = blockIdx.x * blockDim.x + threadIdx.x;
    if (e < E) {
        int d = edge_at(ei, E + e);
        if ((unsigned)d < (unsigned)NN) atomicAdd(&g_cnt[d], 1);
    }
}

__global__ void k_scan_blocks(int n) {
    __shared__ int wsum[32];
    int tid  = threadIdx.x;
    int lane = tid & 31, wid = tid >> 5;
    int i = blockIdx.x * SCAN_B + tid;
    int v = (i < n) ? g_cnt[i] : 0;
    int x = v;
    #pragma unroll
    for (int d = 1; d < 32; d <<= 1) {
        int t = __shfl_up_sync(0xffffffffu, x, d);
        if (lane >= d) x += t;
    }
    if (lane == 31) wsum[wid] = x;
    __syncthreads();
    if (wid == 0) {
        int s = wsum[lane];
        #pragma unroll
        for (int d = 1; d < 32; d <<= 1) {
            int t = __shfl_up_sync(0xffffffffu, s, d);
            if (lane >= d) s += t;
        }
        wsum[lane] = s;
    }
    __syncthreads();
    int woffs = (wid > 0) ? wsum[wid - 1] : 0;
    if (i < n) g_rptr[i] = woffs + x - v;
    if (tid == SCAN_B - 1) g_bsum[blockIdx.x] = wsum[31];
}

__global__ void k_scan_bsum(int nb) {
    __shared__ int s[NB];
    int tid = threadIdx.x;
    if (tid < nb) s[tid] = g_bsum[tid];
    __syncthreads();
    if (tid == 0) {
        int acc = 0;
        for (int i = 0; i < nb; i++) { int t = s[i]; s[i] = acc; acc += t; }
    }
    __syncthreads();
    if (tid < nb) g_bsum[tid] = s[tid];
}

__global__ void k_add_off(int n, int E) {
    int i = blockIdx.x * SCAN_B + threadIdx.x;
    if (i < n) {
        int v = g_rptr[i] + g_bsum[blockIdx.x];
        g_rptr[i] = v;
        g_woff[i] = v;
    }
    if (i == 0) g_rptr[n] = E;
}

__global__ void k_scatter(const void* __restrict__ ei, int E) {
    int e = blockIdx.x * blockDim.x + threadIdx.x;
    if (e < E) {
        int s = edge_at(ei, e);
        int d = edge_at(ei, E + e);
        if ((unsigned)s < (unsigned)NN && (unsigned)d < (unsigned)NN) {
            int p = atomicAdd(&g_woff[d], 1);
            if ((unsigned)p < (unsigned)NE) g_col[p] = s;
        }
    }
}

// ---------------- weight packing: fp32 -> bf16 hi/lo, padded rows ----------
__global__ void k_pack(const float* __restrict__ Wl0, const float* __restrict__ Wr0,
                       const float* __restrict__ Wl1, const float* __restrict__ Wr1) {
    int i = blockIdx.x * blockDim.x + threadIdx.x;
    if (i < 256 * B1U) {
        int k = i / B1U, c = i % B1U;
        float f0 = 0.f, f1 = 0.f;
        if (c < 64) {
            const float* W = (k < 128) ? Wl0 : Wr0;
            int kk = k & 127;
            f0 = W[kk * 128 + 2 * c];
            f1 = W[kk * 128 + 2 * c + 1];
        }
        uint32_t hi, lo;
        split2(f0, f1, hi, lo);
        g_B1h[i] = hi; g_B1l[i] = lo;
    }
    if (i < 256 * B2U) {
        int k = i / B2U, c = i % B2U;
        float f0 = 0.f, f1 = 0.f;
        if (c < 32) {
            const float* W = (k < 128) ? Wl1 : Wr1;
            int kk = k & 127;
            f0 = W[kk * 64 + 2 * c];
            f1 = W[kk * 64 + 2 * c + 1];
        }
        uint32_t hi, lo;
        split2(f0, f1, hi, lo);
        g_B2h[i] = hi; g_B2l[i] = lo;
    }
}

// ---------------- fused SAGE layer: gather-mean + tensor-core GEMM ---------
// Per block: 64-node tile, 256 threads (8 warps).
// Phase A: warp-per-node gather-mean into Agg (fp32 smem).
// Phase B: C = [Agg | own rows] (K=256) @ B via mma.sync bf16 hi/lo split:
//          acc = Ah@Bh + Ah@Bl + Al@Bh   (error ~ bf16_eps^2)
// LAYER 0: S=x,   N=128, out=g_h (bias+relu). LAYER 1: S=g_h, N=64, out=d_out (bias).
template <int LAYER>
__global__ void __launch_bounds__(256) k_fused(
    const float* __restrict__ srcext,
    const float* __restrict__ bias,
    float* __restrict__ outp,
    int M)
{
    constexpr int N     = (LAYER == 0) ? 128 : 64;
    constexpr int NHALF = N / 2;
    constexpr int NT    = NHALF / 8;          // n-tiles per warp (8 or 4)
    constexpr int BROWU = (LAYER == 0) ? B1U : B2U;

    __shared__ float    Agg[64][132];         // fp32 gather result
    __shared__ uint32_t Ahu[64 * 12];         // bf16-hi, row stride 12 u32 (48 B)
    __shared__ uint32_t Alu[64 * 12];         // bf16-lo
    __shared__ uint32_t Bsh[16 * BROWU];      // bf16-hi weights chunk
    __shared__ uint32_t Bsl[16 * BROWU];      // bf16-lo weights chunk

    const float*    S   = (LAYER == 0) ? srcext : g_h;
    const uint32_t* gBh = (LAYER == 0) ? g_B1h : g_B2h;
    const uint32_t* gBl = (LAYER == 0) ? g_B1l : g_B2l;

    int tid  = threadIdx.x;
    int lane = tid & 31, w = tid >> 5;
    int tile0 = blockIdx.x * 64;

    // -------- Phase A: gather-mean into Agg --------
    #pragma unroll 1
    for (int u = 0; u < 8; u++) {
        int r = w * 8 + u;
        int node = tile0 + r;
        float4 acc4 = make_float4(0.f, 0.f, 0.f, 0.f);
        if (node < M) {
            int rs = g_rptr[node], re = g_rptr[node + 1];
            int j = rs;
            for (; j + 4 <= re; j += 4) {
                int s0 = g_col[j], s1 = g_col[j+1], s2 = g_col[j+2], s3 = g_col[j+3];
                float4 v0 = *(const float4*)&S[s0 * 128 + lane * 4];
                float4 v1 = *(const float4*)&S[s1 * 128 + lane * 4];
                float4 v2 = *(const float4*)&S[s2 * 128 + lane * 4];
                float4 v3 = *(const float4*)&S[s3 * 128 + lane * 4];
                acc4.x += v0.x + v1.x + v2.x + v3.x;
                acc4.y += v0.y + v1.y + v2.y + v3.y;
                acc4.z += v0.z + v1.z + v2.z + v3.z;
                acc4.w += v0.w + v1.w + v2.w + v3.w;
            }
            for (; j < re; j++) {
                int s = g_col[j];
                float4 v = *(const float4*)&S[s * 128 + lane * 4];
                acc4.x += v.x; acc4.y += v.y; acc4.z += v.z; acc4.w += v.w;
            }
            int deg = re - rs;
            float inv = 1.0f / (float)(deg > 1 ? deg : 1);
            acc4.x *= inv; acc4.y *= inv; acc4.z *= inv; acc4.w *= inv;
        }
        *(float4*)&Agg[r][lane * 4] = acc4;
    }

    // -------- Phase B: tensor-core GEMM --------
    int wr = (w & 3) * 16;          // warp's 16-row band
    int wc = (w >> 2) * NHALF;      // warp's column half

    float acc[NT][4];
    #pragma unroll
    for (int t = 0; t < NT; t++) {
        acc[t][0] = 0.f; acc[t][1] = 0.f; acc[t][2] = 0.f; acc[t][3] = 0.f;
    }

    // fixed per-warp ldmatrix addresses (smem buffers reused every chunk)
    uint32_t aAddrH = sptr(Ahu) + (wr + (lane & 15)) * 48 + ((lane >> 4) << 4);
    uint32_t aAddrL = sptr(Alu) + (wr + (lane & 15)) * 48 + ((lane >> 4) << 4);
    uint32_t bBase  = (lane & 15) * (BROWU * 4) + (wc + ((lane >> 4) << 3)) * 2;
    uint32_t bAddrH = sptr(Bsh) + bBase;
    uint32_t bAddrL = sptr(Bsl) + bBase;

    int arow = tid >> 2;            // staging row for A
    int akp  = (tid & 3) * 4;       // staging k offset (4 elems)
    int acol = arow * 12 + (tid & 3) * 2;

    for (int kc = 0; kc < 256; kc += 16) {
        __syncthreads();            // Agg ready (1st) / previous compute done

        // stage A chunk: fp32 -> bf16 hi/lo
        {
            float4 v;
            if (kc < 128) {
                v = *(const float4*)&Agg[arow][kc + akp];
            } else {
                int gr = tile0 + arow;
                v = make_float4(0.f, 0.f, 0.f, 0.f);
                if (gr < M) v = *(const float4*)&S[gr * 128 + (kc - 128) + akp];
            }
            uint32_t h0, l0, h1, l1;
            split2(v.x, v.y, h0, l0);
            split2(v.z, v.w, h1, l1);
            Ahu[acol] = h0; Ahu[acol + 1] = h1;
            Alu[acol] = l0; Alu[acol + 1] = l1;
        }
        // stage B chunk: straight copy of prepacked bf16
        {
            int base = kc * BROWU;
            for (int i = tid; i < 16 * BROWU; i += 256) {
                Bsh[i] = gBh[base + i];
                Bsl[i] = gBl[base + i];
            }
        }
        __syncthreads();

        uint32_t ah0, ah1, ah2, ah3, al0, al1, al2, al3;
        LDSM_X4(ah0, ah1, ah2, ah3, aAddrH);
        LDSM_X4(al0, al1, al2, al3, aAddrL);

        #pragma unroll
        for (int p = 0; p < NT / 2; p++) {
            uint32_t bh0, bh1, bh2, bh3, bl0, bl1, bl2, bl3;
            LDSM_X4_T(bh0, bh1, bh2, bh3, bAddrH + p * 32);
            LDSM_X4_T(bl0, bl1, bl2, bl3, bAddrL + p * 32);
            MMA16816(acc[2*p],   ah0, ah1, ah2, ah3, bh0, bh1);
            MMA16816(acc[2*p],   ah0, ah1, ah2, ah3, bl0, bl1);
            MMA16816(acc[2*p],   al0, al1, al2, al3, bh0, bh1);
            MMA16816(acc[2*p+1], ah0, ah1, ah2, ah3, bh2, bh3);
            MMA16816(acc[2*p+1], ah0, ah1, ah2, ah3, bl2, bl3);
            MMA16816(acc[2*p+1], al0, al1, al2, al3, bh2, bh3);
        }
    }

    // -------- epilogue --------
    int r0   = wr + (lane >> 2);
    int col0 = wc + (lane & 3) * 2;
    int gm0  = tile0 + r0;
    int gm1  = gm0 + 8;
    #pragma unroll
    for (int nt = 0; nt < NT; nt++) {
        int col = col0 + nt * 8;
        float b0 = bias[col], b1 = bias[col + 1];
        if (LAYER == 0) {
            if (gm0 < M) {
                float2 o;
                o.x = acc[nt][0] + b0; o.y = acc[nt][1] + b1;
                o.x = o.x > 0.f ? o.x : 0.f;
                o.y = o.y > 0.f ? o.y : 0.f;
                *(float2*)&g_h[gm0 * 128 + col] = o;
            }
            if (gm1 < M) {
                float2 o;
                o.x = acc[nt][2] + b0; o.y = acc[nt][3] + b1;
                o.x = o.x > 0.f ? o.x : 0.f;
                o.y = o.y > 0.f ? o.y : 0.f;
                *(float2*)&g_h[gm1 * 128 + col] = o;
            }
        } else {
            if (gm0 < M) {
                float2 o;
                o.x = acc[nt][0] + b0; o.y = acc[nt][1] + b1;
                *(float2*)&outp[gm0 * 64 + col] = o;
            }
            if (gm1 < M) {
                float2 o;
                o.x = acc[nt][2] + b0; o.y = acc[nt][3] + b1;
                *(float2*)&outp[gm1 * 64 + col] = o;
            }
        }
    }
}

// ---------------- launch (kernel launches ONLY) ----------------------------
extern "C" void kernel_launch(void* const* d_in, const int* in_sizes, int n_in,
                              void* d_out, int out_size) {
    const float* x   = (const float*)d_in[0];
    const void*  ei  = d_in[1];
    const float* Wl0 = (const float*)d_in[2];
    const float* bl0 = (const float*)d_in[3];
    const float* Wr0 = (const float*)d_in[4];
    const float* Wl1 = (const float*)d_in[5];
    const float* bl1 = (const float*)d_in[6];
    const float* Wr1 = (const float*)d_in[7];
    float* out = (float*)d_out;

    int M = in_sizes[0] / 128;      // 100000
    int E = in_sizes[1] / 2;        // 1600000

    k_detect<<<1, 256>>>((const int*)ei);
    k_zero_cnt<<<(M + 255) / 256, 256>>>(M);
    k_hist<<<(E + 255) / 256, 256>>>(ei, E);
    k_scan_blocks<<<NB, SCAN_B>>>(M);
    k_scan_bsum<<<1, 128>>>(NB);
    k_add_off<<<NB, SCAN_B>>>(M, E);
    k_scatter<<<(E + 255) / 256, 256>>>(ei, E);
    k_pack<<<(256 * B1U + 255) / 256, 256>>>(Wl0, Wr0, Wl1, Wr1);

    int tiles = (M + 63) / 64;
    k_fused<0><<<tiles, 256>>>(x, bl0, nullptr, M);
    k_fused<1><<<tiles, 256>>>(nullptr, bl1, out, M);
}

// round 8
// speedup vs baseline: 1.5178x; 1.2219x over previous
#include <cuda_runtime.h>
#include <cuda_bf16.h>
#include <stdint.h>

#define NN 100000
#define NE 1600000
#define SCAN_B 1024
#define NB ((NN + SCAN_B - 1) / SCAN_B)   // 98

// B1: 256x128 -> padded-packed u32 [256][68] (64 data + 4 pad)
// B2: 128x128 ([Wl1 | Wr1]) -> padded-packed u32 [128][68]
#define B1U 68
#define B2U 68

// ---------------- scratch (device globals) ---------------------------------
__device__ int   g_is64;
__device__ int   g_cnt[NN];
__device__ int   g_rptr[NN + 1];
__device__ int   g_woff[NN];
__device__ int   g_bsum[NB];
__device__ int   g_col[NE];
__device__ __align__(16) float    g_h[NN * 128];
__device__ __align__(16) float    g_z1[NN * 64];
__device__ __align__(16) float    g_r1[NN * 64];
__device__ __align__(16) uint32_t g_B1h[256 * B1U];
__device__ __align__(16) uint32_t g_B1l[256 * B1U];
__device__ __align__(16) uint32_t g_B2h[128 * B2U];
__device__ __align__(16) uint32_t g_B2l[128 * B2U];

// ---------------- helpers --------------------------------------------------
__device__ __forceinline__ uint32_t sptr(const void* p) {
    uint32_t a;
    asm("{ .reg .u64 t; cvta.to.shared.u64 t, %1; cvt.u32.u64 %0, t; }"
        : "=r"(a) : "l"(p));
    return a;
}

#define LDSM_X4(r0,r1,r2,r3,addr) \
    asm volatile("ldmatrix.sync.aligned.m8n8.x4.shared.b16 {%0,%1,%2,%3}, [%4];" \
        : "=r"(r0),"=r"(r1),"=r"(r2),"=r"(r3) : "r"(addr))

#define LDSM_X4_T(r0,r1,r2,r3,addr) \
    asm volatile("ldmatrix.sync.aligned.m8n8.x4.trans.shared.b16 {%0,%1,%2,%3}, [%4];" \
        : "=r"(r0),"=r"(r1),"=r"(r2),"=r"(r3) : "r"(addr))

#define MMA16816(c, a0,a1,a2,a3, b0,b1) \
    asm volatile("mma.sync.aligned.m16n8k16.row.col.f32.bf16.bf16.f32 " \
        "{%0,%1,%2,%3},{%4,%5,%6,%7},{%8,%9},{%0,%1,%2,%3};" \
        : "+f"((c)[0]),"+f"((c)[1]),"+f"((c)[2]),"+f"((c)[3]) \
        : "r"(a0),"r"(a1),"r"(a2),"r"(a3),"r"(b0),"r"(b1))

__device__ __forceinline__ void split2(float f0, float f1, uint32_t& hi, uint32_t& lo) {
    __nv_bfloat162 h, l;
    h.x = __float2bfloat16(f0);
    h.y = __float2bfloat16(f1);
    l.x = __float2bfloat16(f0 - __bfloat162float(h.x));
    l.y = __float2bfloat16(f1 - __bfloat162float(h.y));
    hi = *reinterpret_cast<uint32_t*>(&h);
    lo = *reinterpret_cast<uint32_t*>(&l);
}

// ---------------- edge_index dtype detection -------------------------------
__global__ void k_detect(const int* __restrict__ ei32) {
    __shared__ int nz;
    if (threadIdx.x == 0) nz = 0;
    __syncthreads();
    int v = 0;
    for (int i = threadIdx.x; i < 1024; i += 256) v |= ei32[2 * i + 1];
    if (v) atomicOr(&nz, 1);
    __syncthreads();
    if (threadIdx.x == 0) g_is64 = (nz == 0) ? 1 : 0;
}

__device__ __forceinline__ int edge_at(const void* ei, int idx) {
    return g_is64 ? (int)((const long long*)ei)[idx] : ((const int*)ei)[idx];
}

// ---------------- CSR build ----------------
__global__ void k_zero_cnt(int n) {
    int i = blockIdx.x * blockDim.x + threadIdx.x;
    if (i < n) g_cnt[i] = 0;
}

__global__ void k_hist(const void* __restrict__ ei, int E) {
    int e = blockIdx.x * blockDim.x + threadIdx.x;
    if (e < E) {
        int d = edge_at(ei, E + e);
        if ((unsigned)d < (unsigned)NN) atomicAdd(&g_cnt[d], 1);
    }
}

__global__ void k_scan_blocks(int n) {
    __shared__ int wsum[32];
    int tid  = threadIdx.x;
    int lane = tid & 31, wid = tid >> 5;
    int i = blockIdx.x * SCAN_B + tid;
    int v = (i < n) ? g_cnt[i] : 0;
    int x = v;
    #pragma unroll
    for (int d = 1; d < 32; d <<= 1) {
        int t = __shfl_up_sync(0xffffffffu, x, d);
        if (lane >= d) x += t;
    }
    if (lane == 31) wsum[wid] = x;
    __syncthreads();
    if (wid == 0) {
        int s = wsum[lane];
        #pragma unroll
        for (int d = 1; d < 32; d <<= 1) {
            int t = __shfl_up_sync(0xffffffffu, s, d);
            if (lane >= d) s += t;
        }
        wsum[lane] = s;
    }
    __syncthreads();
    int woffs = (wid > 0) ? wsum[wid - 1] : 0;
    if (i < n) g_rptr[i] = woffs + x - v;
    if (tid == SCAN_B - 1) g_bsum[blockIdx.x] = wsum[31];
}

__global__ void k_scan_bsum(int nb) {
    __shared__ int s[NB];
    int tid = threadIdx.x;
    if (tid < nb) s[tid] = g_bsum[tid];
    __syncthreads();
    if (tid == 0) {
        int acc = 0;
        for (int i = 0; i < nb; i++) { int t = s[i]; s[i] = acc; acc += t; }
    }
    __syncthreads();
    if (tid < nb) g_bsum[tid] = s[tid];
}

__global__ void k_add_off(int n, int E) {
    int i = blockIdx.x * SCAN_B + threadIdx.x;
    if (i < n) {
        int v = g_rptr[i] + g_bsum[blockIdx.x];
        g_rptr[i] = v;
        g_woff[i] = v;
    }
    if (i == 0) g_rptr[n] = E;
}

__global__ void k_scatter(const void* __restrict__ ei, int E) {
    int e = blockIdx.x * blockDim.x + threadIdx.x;
    if (e < E) {
        int s = edge_at(ei, e);
        int d = edge_at(ei, E + e);
        if ((unsigned)s < (unsigned)NN && (unsigned)d < (unsigned)NN) {
            int p = atomicAdd(&g_woff[d], 1);
            if ((unsigned)p < (unsigned)NE) g_col[p] = s;
        }
    }
}

// ---------------- weight packing: fp32 -> bf16 hi/lo, padded rows ----------
__global__ void k_pack(const float* __restrict__ Wl0, const float* __restrict__ Wr0,
                       const float* __restrict__ Wl1, const float* __restrict__ Wr1) {
    int i = blockIdx.x * blockDim.x + threadIdx.x;
    if (i < 256 * B1U) {
        int k = i / B1U, c = i % B1U;
        float f0 = 0.f, f1 = 0.f;
        if (c < 64) {
            const float* W = (k < 128) ? Wl0 : Wr0;
            int kk = k & 127;
            f0 = W[kk * 128 + 2 * c];
            f1 = W[kk * 128 + 2 * c + 1];
        }
        uint32_t hi, lo;
        split2(f0, f1, hi, lo);
        g_B1h[i] = hi; g_B1l[i] = lo;
    }
    // B2 = [Wl1 | Wr1]: K=128 rows, 128 cols (64 from each)
    if (i < 128 * B2U) {
        int k = i / B2U, c = i % B2U;
        float f0 = 0.f, f1 = 0.f;
        if (c < 32) {
            f0 = Wl1[k * 64 + 2 * c];
            f1 = Wl1[k * 64 + 2 * c + 1];
        } else if (c < 64) {
            int cc = c - 32;
            f0 = Wr1[k * 64 + 2 * cc];
            f1 = Wr1[k * 64 + 2 * cc + 1];
        }
        uint32_t hi, lo;
        split2(f0, f1, hi, lo);
        g_B2h[i] = hi; g_B2l[i] = lo;
    }
}

// ---------------- layer 1: fused gather-mean + tensor-core GEMM ------------
__global__ void __launch_bounds__(256) k_fused0(
    const float* __restrict__ x,
    const float* __restrict__ bias,
    int M)
{
    __shared__ float    Agg[64][132];
    __shared__ __align__(16) uint32_t Ahu[64 * 12];
    __shared__ __align__(16) uint32_t Alu[64 * 12];
    __shared__ __align__(16) uint32_t Bsh[16 * B1U];
    __shared__ __align__(16) uint32_t Bsl[16 * B1U];

    int tid  = threadIdx.x;
    int lane = tid & 31, w = tid >> 5;
    int tile0 = blockIdx.x * 64;

    // Phase A: gather-mean of x into Agg
    #pragma unroll 1
    for (int u = 0; u < 8; u++) {
        int r = w * 8 + u;
        int node = tile0 + r;
        float4 acc4 = make_float4(0.f, 0.f, 0.f, 0.f);
        if (node < M) {
            int rs = g_rptr[node], re = g_rptr[node + 1];
            int j = rs;
            for (; j + 4 <= re; j += 4) {
                int s0 = g_col[j], s1 = g_col[j+1], s2 = g_col[j+2], s3 = g_col[j+3];
                float4 v0 = *(const float4*)&x[s0 * 128 + lane * 4];
                float4 v1 = *(const float4*)&x[s1 * 128 + lane * 4];
                float4 v2 = *(const float4*)&x[s2 * 128 + lane * 4];
                float4 v3 = *(const float4*)&x[s3 * 128 + lane * 4];
                acc4.x += v0.x + v1.x + v2.x + v3.x;
                acc4.y += v0.y + v1.y + v2.y + v3.y;
                acc4.z += v0.z + v1.z + v2.z + v3.z;
                acc4.w += v0.w + v1.w + v2.w + v3.w;
            }
            for (; j < re; j++) {
                int s = g_col[j];
                float4 v = *(const float4*)&x[s * 128 + lane * 4];
                acc4.x += v.x; acc4.y += v.y; acc4.z += v.z; acc4.w += v.w;
            }
            int deg = re - rs;
            float inv = 1.0f / (float)(deg > 1 ? deg : 1);
            acc4.x *= inv; acc4.y *= inv; acc4.z *= inv; acc4.w *= inv;
        }
        *(float4*)&Agg[r][lane * 4] = acc4;
    }

    // Phase B: [Agg | x rows] (K=256) @ B1 -> relu(+bias) -> g_h
    int wr = (w & 3) * 16;
    int wc = (w >> 2) * 64;

    float acc[8][4];
    #pragma unroll
    for (int t = 0; t < 8; t++) {
        acc[t][0] = 0.f; acc[t][1] = 0.f; acc[t][2] = 0.f; acc[t][3] = 0.f;
    }

    uint32_t aAddrH = sptr(Ahu) + (wr + (lane & 15)) * 48 + ((lane >> 4) << 4);
    uint32_t aAddrL = sptr(Alu) + (wr + (lane & 15)) * 48 + ((lane >> 4) << 4);
    uint32_t bBase  = (lane & 15) * (B1U * 4) + (wc + ((lane >> 4) << 3)) * 2;
    uint32_t bAddrH = sptr(Bsh) + bBase;
    uint32_t bAddrL = sptr(Bsl) + bBase;

    int arow = tid >> 2;
    int akp  = (tid & 3) * 4;
    int acol = arow * 12 + (tid & 3) * 2;

    for (int kc = 0; kc < 256; kc += 16) {
        __syncthreads();
        {
            float4 v;
            if (kc < 128) {
                v = *(const float4*)&Agg[arow][kc + akp];
            } else {
                int gr = tile0 + arow;
                v = make_float4(0.f, 0.f, 0.f, 0.f);
                if (gr < M) v = *(const float4*)&x[gr * 128 + (kc - 128) + akp];
            }
            uint32_t h0, l0, h1, l1;
            split2(v.x, v.y, h0, l0);
            split2(v.z, v.w, h1, l1);
            Ahu[acol] = h0; Ahu[acol + 1] = h1;
            Alu[acol] = l0; Alu[acol + 1] = l1;
        }
        {
            const uint4* s4h = (const uint4*)(g_B1h + kc * B1U);
            const uint4* s4l = (const uint4*)(g_B1l + kc * B1U);
            #pragma unroll
            for (int i = tid; i < 16 * B1U / 4; i += 256) {
                ((uint4*)Bsh)[i] = s4h[i];
                ((uint4*)Bsl)[i] = s4l[i];
            }
        }
        __syncthreads();

        uint32_t ah0, ah1, ah2, ah3, al0, al1, al2, al3;
        LDSM_X4(ah0, ah1, ah2, ah3, aAddrH);
        LDSM_X4(al0, al1, al2, al3, aAddrL);

        #pragma unroll
        for (int p = 0; p < 4; p++) {
            uint32_t bh0, bh1, bh2, bh3, bl0, bl1, bl2, bl3;
            LDSM_X4_T(bh0, bh1, bh2, bh3, bAddrH + p * 32);
            LDSM_X4_T(bl0, bl1, bl2, bl3, bAddrL + p * 32);
            MMA16816(acc[2*p],   ah0, ah1, ah2, ah3, bh0, bh1);
            MMA16816(acc[2*p],   ah0, ah1, ah2, ah3, bl0, bl1);
            MMA16816(acc[2*p],   al0, al1, al2, al3, bh0, bh1);
            MMA16816(acc[2*p+1], ah0, ah1, ah2, ah3, bh2, bh3);
            MMA16816(acc[2*p+1], ah0, ah1, ah2, ah3, bl2, bl3);
            MMA16816(acc[2*p+1], al0, al1, al2, al3, bh2, bh3);
        }
    }

    int r0   = wr + (lane >> 2);
    int col0 = wc + (lane & 3) * 2;
    int gm0  = tile0 + r0;
    int gm1  = gm0 + 8;
    #pragma unroll
    for (int nt = 0; nt < 8; nt++) {
        int col = col0 + nt * 8;
        float b0 = bias[col], b1 = bias[col + 1];
        if (gm0 < M) {
            float2 o;
            o.x = acc[nt][0] + b0; o.y = acc[nt][1] + b1;
            o.x = o.x > 0.f ? o.x : 0.f;
            o.y = o.y > 0.f ? o.y : 0.f;
            *(float2*)&g_h[gm0 * 128 + col] = o;
        }
        if (gm1 < M) {
            float2 o;
            o.x = acc[nt][2] + b0; o.y = acc[nt][3] + b1;
            o.x = o.x > 0.f ? o.x : 0.f;
            o.y = o.y > 0.f ? o.y : 0.f;
            *(float2*)&g_h[gm1 * 128 + col] = o;
        }
    }
}

// ---------------- layer 2a: dense GEMM h @ [Wl1|Wr1] -> z1 | r1 ------------
__global__ void __launch_bounds__(256) k_dense(int M) {
    __shared__ __align__(16) uint32_t Ahu[64 * 12];
    __shared__ __align__(16) uint32_t Alu[64 * 12];
    __shared__ __align__(16) uint32_t Bsh[16 * B2U];
    __shared__ __align__(16) uint32_t Bsl[16 * B2U];

    int tid  = threadIdx.x;
    int lane = tid & 31, w = tid >> 5;
    int tile0 = blockIdx.x * 64;

    int wr = (w & 3) * 16;
    int wc = (w >> 2) * 64;

    float acc[8][4];
    #pragma unroll
    for (int t = 0; t < 8; t++) {
        acc[t][0] = 0.f; acc[t][1] = 0.f; acc[t][2] = 0.f; acc[t][3] = 0.f;
    }

    uint32_t aAddrH = sptr(Ahu) + (wr + (lane & 15)) * 48 + ((lane >> 4) << 4);
    uint32_t aAddrL = sptr(Alu) + (wr + (lane & 15)) * 48 + ((lane >> 4) << 4);
    uint32_t bBase  = (lane & 15) * (B2U * 4) + (wc + ((lane >> 4) << 3)) * 2;
    uint32_t bAddrH = sptr(Bsh) + bBase;
    uint32_t bAddrL = sptr(Bsl) + bBase;

    int arow = tid >> 2;
    int akp  = (tid & 3) * 4;
    int acol = arow * 12 + (tid & 3) * 2;

    for (int kc = 0; kc < 128; kc += 16) {
        if (kc) __syncthreads();
        {
            int gr = tile0 + arow;
            float4 v = make_float4(0.f, 0.f, 0.f, 0.f);
            if (gr < M) v = *(const float4*)&g_h[gr * 128 + kc + akp];
            uint32_t h0, l0, h1, l1;
            split2(v.x, v.y, h0, l0);
            split2(v.z, v.w, h1, l1);
            Ahu[acol] = h0; Ahu[acol + 1] = h1;
            Alu[acol] = l0; Alu[acol + 1] = l1;
        }
        {
            const uint4* s4h = (const uint4*)(g_B2h + kc * B2U);
            const uint4* s4l = (const uint4*)(g_B2l + kc * B2U);
            #pragma unroll
            for (int i = tid; i < 16 * B2U / 4; i += 256) {
                ((uint4*)Bsh)[i] = s4h[i];
                ((uint4*)Bsl)[i] = s4l[i];
            }
        }
        __syncthreads();

        uint32_t ah0, ah1, ah2, ah3, al0, al1, al2, al3;
        LDSM_X4(ah0, ah1, ah2, ah3, aAddrH);
        LDSM_X4(al0, al1, al2, al3, aAddrL);

        #pragma unroll
        for (int p = 0; p < 4; p++) {
            uint32_t bh0, bh1, bh2, bh3, bl0, bl1, bl2, bl3;
            LDSM_X4_T(bh0, bh1, bh2, bh3, bAddrH + p * 32);
            LDSM_X4_T(bl0, bl1, bl2, bl3, bAddrL + p * 32);
            MMA16816(acc[2*p],   ah0, ah1, ah2, ah3, bh0, bh1);
            MMA16816(acc[2*p],   ah0, ah1, ah2, ah3, bl0, bl1);
            MMA16816(acc[2*p],   al0, al1, al2, al3, bh0, bh1);
            MMA16816(acc[2*p+1], ah0, ah1, ah2, ah3, bh2, bh3);
            MMA16816(acc[2*p+1], ah0, ah1, ah2, ah3, bl2, bl3);
            MMA16816(acc[2*p+1], al0, al1, al2, al3, bh2, bh3);
        }
    }

    int r0   = wr + (lane >> 2);
    int col0 = wc + (lane & 3) * 2;
    int gm0  = tile0 + r0;
    int gm1  = gm0 + 8;
    #pragma unroll
    for (int nt = 0; nt < 8; nt++) {
        int col = col0 + nt * 8;
        float* dst = (col < 64) ? g_z1 : g_r1;
        int c = col & 63;
        if (gm0 < M) {
            float2 o; o.x = acc[nt][0]; o.y = acc[nt][1];
            *(float2*)&dst[gm0 * 64 + c] = o;
        }
        if (gm1 < M) {
            float2 o; o.x = acc[nt][2]; o.y = acc[nt][3];
            *(float2*)&dst[gm1 * 64 + c] = o;
        }
    }
}

// ---------------- layer 2b: out = mean_agg(z1) + bl1 + r1 ------------------
__global__ void k_out(const float* __restrict__ bias, float* __restrict__ out, int n) {
    int warp = (blockIdx.x * blockDim.x + threadIdx.x) >> 5;
    int lane = threadIdx.x & 31;
    if (warp >= n) return;
    int rs = g_rptr[warp], re = g_rptr[warp + 1];
    int d0 = lane * 2;
    float2 acc = make_float2(0.f, 0.f);
    int j = rs;
    for (; j + 4 <= re; j += 4) {
        int s0 = g_col[j], s1 = g_col[j + 1], s2 = g_col[j + 2], s3 = g_col[j + 3];
        float2 v0 = *(const float2*)&g_z1[s0 * 64 + d0];
        float2 v1 = *(const float2*)&g_z1[s1 * 64 + d0];
        float2 v2 = *(const float2*)&g_z1[s2 * 64 + d0];
        float2 v3 = *(const float2*)&g_z1[s3 * 64 + d0];
        acc.x += v0.x + v1.x + v2.x + v3.x;
        acc.y += v0.y + v1.y + v2.y + v3.y;
    }
    for (; j < re; j++) {
        int s = g_col[j];
        float2 v = *(const float2*)&g_z1[s * 64 + d0];
        acc.x += v.x; acc.y += v.y;
    }
    int deg = re - rs;
    float inv = 1.0f / (float)(deg > 1 ? deg : 1);
    float2 r = *(const float2*)&g_r1[warp * 64 + d0];
    float2 o;
    o.x = acc.x * inv + bias[d0]     + r.x;
    o.y = acc.y * inv + bias[d0 + 1] + r.y;
    *(float2*)&out[warp * 64 + d0] = o;
}

// ---------------- launch (kernel launches ONLY) ----------------------------
extern "C" void kernel_launch(void* const* d_in, const int* in_sizes, int n_in,
                              void* d_out, int out_size) {
    const float* x   = (const float*)d_in[0];
    const void*  ei  = d_in[1];
    const float* Wl0 = (const float*)d_in[2];
    const float* bl0 = (const float*)d_in[3];
    const float* Wr0 = (const float*)d_in[4];
    const float* Wl1 = (const float*)d_in[5];
    const float* bl1 = (const float*)d_in[6];
    const float* Wr1 = (const float*)d_in[7];
    float* out = (float*)d_out;

    int M = in_sizes[0] / 128;      // 100000
    int E = in_sizes[1] / 2;        // 1600000

    k_detect<<<1, 256>>>((const int*)ei);
    k_zero_cnt<<<(M + 255) / 256, 256>>>(M);
    k_hist<<<(E + 255) / 256, 256>>>(ei, E);
    k_scan_blocks<<<NB, SCAN_B>>>(M);
    k_scan_bsum<<<1, 128>>>(NB);
    k_add_off<<<NB, SCAN_B>>>(M, E);
    k_scatter<<<(E + 255) / 256, 256>>>(ei, E);
    k_pack<<<(256 * B1U + 255) / 256, 256>>>(Wl0, Wr0, Wl1, Wr1);

    int tiles = (M + 63) / 64;
    k_fused0<<<tiles, 256>>>(x, bl0, M);
    k_dense<<<tiles, 256>>>(M);
    k_out<<<(M + 7) / 8, 256>>>(bl1, out, M);
}

// round 13
// speedup vs baseline: 1.6218x; 1.0685x over previous
#include <cuda_runtime.h>
#include <cuda_bf16.h>
#include <stdint.h>

#define NN 100000
#define NE 1600000
#define SCAN_B 1024
#define NB ((NN + SCAN_B - 1) / SCAN_B)   // 98

// B1: 256x128 -> padded-packed u32 [256][68] (64 data + 4 pad)
// B2: 128x128 ([Wl1 | Wr1]) -> padded-packed u32 [128][68]
#define B1U 68
#define B2U 68

// ---------------- scratch (device globals) ---------------------------------
__device__ int   g_is64;
__device__ int   g_cnt[NN];
__device__ int   g_rptr[NN + 1];
__device__ int   g_woff[NN];
__device__ int   g_bsum[NB];
__device__ int   g_col[NE];
__device__ __align__(16) float    g_z1[NN * 64];
__device__ __align__(16) float    g_r1[NN * 64];
__device__ __align__(16) uint32_t g_B1h[256 * B1U];
__device__ __align__(16) uint32_t g_B1l[256 * B1U];
__device__ __align__(16) uint32_t g_B2h[128 * B2U];
__device__ __align__(16) uint32_t g_B2l[128 * B2U];

// ---------------- helpers --------------------------------------------------
__device__ __forceinline__ uint32_t sptr(const void* p) {
    uint32_t a;
    asm("{ .reg .u64 t; cvta.to.shared.u64 t, %1; cvt.u32.u64 %0, t; }"
        : "=r"(a) : "l"(p));
    return a;
}

#define LDSM_X4(r0,r1,r2,r3,addr) \
    asm volatile("ldmatrix.sync.aligned.m8n8.x4.shared.b16 {%0,%1,%2,%3}, [%4];" \
        : "=r"(r0),"=r"(r1),"=r"(r2),"=r"(r3) : "r"(addr))

#define LDSM_X4_T(r0,r1,r2,r3,addr) \
    asm volatile("ldmatrix.sync.aligned.m8n8.x4.trans.shared.b16 {%0,%1,%2,%3}, [%4];" \
        : "=r"(r0),"=r"(r1),"=r"(r2),"=r"(r3) : "r"(addr))

#define MMA16816(c, a0,a1,a2,a3, b0,b1) \
    asm volatile("mma.sync.aligned.m16n8k16.row.col.f32.bf16.bf16.f32 " \
        "{%0,%1,%2,%3},{%4,%5,%6,%7},{%8,%9},{%0,%1,%2,%3};" \
        : "+f"((c)[0]),"+f"((c)[1]),"+f"((c)[2]),"+f"((c)[3]) \
        : "r"(a0),"r"(a1),"r"(a2),"r"(a3),"r"(b0),"r"(b1))

__device__ __forceinline__ void split2(float f0, float f1, uint32_t& hi, uint32_t& lo) {
    __nv_bfloat162 h, l;
    h.x = __float2bfloat16(f0);
    h.y = __float2bfloat16(f1);
    l.x = __float2bfloat16(f0 - __bfloat162float(h.x));
    l.y = __float2bfloat16(f1 - __bfloat162float(h.y));
    hi = *reinterpret_cast<uint32_t*>(&h);
    lo = *reinterpret_cast<uint32_t*>(&l);
}

// ---------------- edge_index dtype detection -------------------------------
__global__ void k_detect(const int* __restrict__ ei32) {
    __shared__ int nz;
    if (threadIdx.x == 0) nz = 0;
    __syncthreads();
    int v = 0;
    for (int i = threadIdx.x; i < 1024; i += 256) v |= ei32[2 * i + 1];
    if (v) atomicOr(&nz, 1);
    __syncthreads();
    if (threadIdx.x == 0) g_is64 = (nz == 0) ? 1 : 0;
}

__device__ __forceinline__ int edge_at(const void* ei, int idx) {
    return g_is64 ? (int)((const long long*)ei)[idx] : ((const int*)ei)[idx];
}

// ---------------- CSR build ----------------
__global__ void k_zero_cnt(int n) {
    int i = blockIdx.x * blockDim.x + threadIdx.x;
    if (i < n) g_cnt[i] = 0;
}

__global__ void k_hist(const void* __restrict__ ei, int E) {
    int e = blockIdx.x * blockDim.x + threadIdx.x;
    if (e < E) {
        int d = edge_at(ei, E + e);
        if ((unsigned)d < (unsigned)NN) atomicAdd(&g_cnt[d], 1);
    }
}

__global__ void k_scan_blocks(int n) {
    __shared__ int wsum[32];
    int tid  = threadIdx.x;
    int lane = tid & 31, wid = tid >> 5;
    int i = blockIdx.x * SCAN_B + tid;
    int v = (i < n) ? g_cnt[i] : 0;
    int x = v;
    #pragma unroll
    for (int d = 1; d < 32; d <<= 1) {
        int t = __shfl_up_sync(0xffffffffu, x, d);
        if (lane >= d) x += t;
    }
    if (lane == 31) wsum[wid] = x;
    __syncthreads();
    if (wid == 0) {
        int s = wsum[lane];
        #pragma unroll
        for (int d = 1; d < 32; d <<= 1) {
            int t = __shfl_up_sync(0xffffffffu, s, d);
            if (lane >= d) s += t;
        }
        wsum[lane] = s;
    }
    __syncthreads();
    int woffs = (wid > 0) ? wsum[wid - 1] : 0;
    if (i < n) g_rptr[i] = woffs + x - v;
    if (tid == SCAN_B - 1) g_bsum[blockIdx.x] = wsum[31];
}

__global__ void k_scan_bsum(int nb) {
    __shared__ int s[NB];
    int tid = threadIdx.x;
    if (tid < nb) s[tid] = g_bsum[tid];
    __syncthreads();
    if (tid == 0) {
        int acc = 0;
        for (int i = 0; i < nb; i++) { int t = s[i]; s[i] = acc; acc += t; }
    }
    __syncthreads();
    if (tid < nb) g_bsum[tid] = s[tid];
}

__global__ void k_add_off(int n, int E) {
    int i = blockIdx.x * SCAN_B + threadIdx.x;
    if (i < n) {
        int v = g_rptr[i] + g_bsum[blockIdx.x];
        g_rptr[i] = v;
        g_woff[i] = v;
    }
    if (i == 0) g_rptr[n] = E;
}

__global__ void k_scatter(const void* __restrict__ ei, int E) {
    int e = blockIdx.x * blockDim.x + threadIdx.x;
    if (e < E) {
        int s = edge_at(ei, e);
        int d = edge_at(ei, E + e);
        if ((unsigned)s < (unsigned)NN && (unsigned)d < (unsigned)NN) {
            int p = atomicAdd(&g_woff[d], 1);
            if ((unsigned)p < (unsigned)NE) g_col[p] = s;
        }
    }
}

// ---------------- weight packing: fp32 -> bf16 hi/lo, padded rows ----------
__global__ void k_pack(const float* __restrict__ Wl0, const float* __restrict__ Wr0,
                       const float* __restrict__ Wl1, const float* __restrict__ Wr1) {
    int i = blockIdx.x * blockDim.x + threadIdx.x;
    if (i < 256 * B1U) {
        int k = i / B1U, c = i % B1U;
        float f0 = 0.f, f1 = 0.f;
        if (c < 64) {
            const float* W = (k < 128) ? Wl0 : Wr0;
            int kk = k & 127;
            f0 = W[kk * 128 + 2 * c];
            f1 = W[kk * 128 + 2 * c + 1];
        }
        uint32_t hi, lo;
        split2(f0, f1, hi, lo);
        g_B1h[i] = hi; g_B1l[i] = lo;
    }
    // B2 = [Wl1 | Wr1]: K=128 rows, 128 cols (64 from each)
    if (i < 128 * B2U) {
        int k = i / B2U, c = i % B2U;
        float f0 = 0.f, f1 = 0.f;
        if (c < 32) {
            f0 = Wl1[k * 64 + 2 * c];
            f1 = Wl1[k * 64 + 2 * c + 1];
        } else if (c < 64) {
            int cc = c - 32;
            f0 = Wr1[k * 64 + 2 * cc];
            f1 = Wr1[k * 64 + 2 * cc + 1];
        }
        uint32_t hi, lo;
        split2(f0, f1, hi, lo);
        g_B2h[i] = hi; g_B2l[i] = lo;
    }
}

// ---------------- mega kernel: gather + GEMM1(+relu) + GEMM2 ---------------
// Per block (64-node tile, 256 threads):
//  A: Agg = mean-agg(x) over CSR               (fp32 smem)
//  B: h = relu([Agg | x] @ B1 + bl0)           (tensor cores, h -> Agg smem)
//  C: [z1 | r1] = h @ [Wl1 | Wr1]              (tensor cores, from smem)
// h never touches global memory.
__global__ void __launch_bounds__(256) k_layer1(
    const float* __restrict__ x,
    const float* __restrict__ bias,
    int M)
{
    __shared__ float    Agg[64][132];
    __shared__ __align__(16) uint32_t Ahu[64 * 12];
    __shared__ __align__(16) uint32_t Alu[64 * 12];
    __shared__ __align__(16) uint32_t Bsh[16 * B1U];
    __shared__ __align__(16) uint32_t Bsl[16 * B1U];

    int tid  = threadIdx.x;
    int lane = tid & 31, w = tid >> 5;
    int tile0 = blockIdx.x * 64;

    // -------- Phase A: gather-mean of x into Agg --------
    #pragma unroll 1
    for (int u = 0; u < 8; u++) {
        int r = w * 8 + u;
        int node = tile0 + r;
        float4 acc4 = make_float4(0.f, 0.f, 0.f, 0.f);
        if (node < M) {
            int rs = g_rptr[node], re = g_rptr[node + 1];
            int j = rs;
            for (; j + 4 <= re; j += 4) {
                int s0 = g_col[j], s1 = g_col[j+1], s2 = g_col[j+2], s3 = g_col[j+3];
                float4 v0 = *(const float4*)&x[s0 * 128 + lane * 4];
                float4 v1 = *(const float4*)&x[s1 * 128 + lane * 4];
                float4 v2 = *(const float4*)&x[s2 * 128 + lane * 4];
                float4 v3 = *(const float4*)&x[s3 * 128 + lane * 4];
                acc4.x += v0.x + v1.x + v2.x + v3.x;
                acc4.y += v0.y + v1.y + v2.y + v3.y;
                acc4.z += v0.z + v1.z + v2.z + v3.z;
                acc4.w += v0.w + v1.w + v2.w + v3.w;
            }
            for (; j < re; j++) {
                int s = g_col[j];
                float4 v = *(const float4*)&x[s * 128 + lane * 4];
                acc4.x += v.x; acc4.y += v.y; acc4.z += v.z; acc4.w += v.w;
            }
            int deg = re - rs;
            float inv = 1.0f / (float)(deg > 1 ? deg : 1);
            acc4.x *= inv; acc4.y *= inv; acc4.z *= inv; acc4.w *= inv;
        }
        *(float4*)&Agg[r][lane * 4] = acc4;
    }

    // -------- per-warp MMA geometry (shared by both GEMMs) --------
    int wr = (w & 3) * 16;
    int wc = (w >> 2) * 64;

    uint32_t aAddrH = sptr(Ahu) + (wr + (lane & 15)) * 48 + ((lane >> 4) << 4);
    uint32_t aAddrL = sptr(Alu) + (wr + (lane & 15)) * 48 + ((lane >> 4) << 4);
    uint32_t bBase  = (lane & 15) * (B1U * 4) + (wc + ((lane >> 4) << 3)) * 2;
    uint32_t bAddrH = sptr(Bsh) + bBase;
    uint32_t bAddrL = sptr(Bsl) + bBase;

    int arow = tid >> 2;
    int akp  = (tid & 3) * 4;
    int acol = arow * 12 + (tid & 3) * 2;

    int r0   = wr + (lane >> 2);
    int col0 = wc + (lane & 3) * 2;
    int gm0  = tile0 + r0;
    int gm1  = gm0 + 8;

    // -------- Phase B: GEMM1 [Agg | x] (K=256) @ B1 --------
    float acc[8][4];
    #pragma unroll
    for (int t = 0; t < 8; t++) {
        acc[t][0] = 0.f; acc[t][1] = 0.f; acc[t][2] = 0.f; acc[t][3] = 0.f;
    }

    for (int kc = 0; kc < 256; kc += 16) {
        __syncthreads();
        {
            float4 v;
            if (kc < 128) {
                v = *(const float4*)&Agg[arow][kc + akp];
            } else {
                int gr = tile0 + arow;
                v = make_float4(0.f, 0.f, 0.f, 0.f);
                if (gr < M) v = *(const float4*)&x[gr * 128 + (kc - 128) + akp];
            }
            uint32_t h0, l0, h1, l1;
            split2(v.x, v.y, h0, l0);
            split2(v.z, v.w, h1, l1);
            Ahu[acol] = h0; Ahu[acol + 1] = h1;
            Alu[acol] = l0; Alu[acol + 1] = l1;
        }
        {
            const uint4* s4h = (const uint4*)(g_B1h + kc * B1U);
            const uint4* s4l = (const uint4*)(g_B1l + kc * B1U);
            #pragma unroll
            for (int i = tid; i < 16 * B1U / 4; i += 256) {
                ((uint4*)Bsh)[i] = s4h[i];
                ((uint4*)Bsl)[i] = s4l[i];
            }
        }
        __syncthreads();

        uint32_t ah0, ah1, ah2, ah3, al0, al1, al2, al3;
        LDSM_X4(ah0, ah1, ah2, ah3, aAddrH);
        LDSM_X4(al0, al1, al2, al3, aAddrL);

        #pragma unroll
        for (int p = 0; p < 4; p++) {
            uint32_t bh0, bh1, bh2, bh3, bl0, bl1, bl2, bl3;
            LDSM_X4_T(bh0, bh1, bh2, bh3, bAddrH + p * 32);
            LDSM_X4_T(bl0, bl1, bl2, bl3, bAddrL + p * 32);
            MMA16816(acc[2*p],   ah0, ah1, ah2, ah3, bh0, bh1);
            MMA16816(acc[2*p],   ah0, ah1, ah2, ah3, bl0, bl1);
            MMA16816(acc[2*p],   al0, al1, al2, al3, bh0, bh1);
            MMA16816(acc[2*p+1], ah0, ah1, ah2, ah3, bh2, bh3);
            MMA16816(acc[2*p+1], ah0, ah1, ah2, ah3, bl2, bl3);
            MMA16816(acc[2*p+1], al0, al1, al2, al3, bh2, bh3);
        }
    }

    // -------- h = relu(acc + bias) -> Agg smem (Agg dead after kc=112) ------
    // All warps passed the kc=240 barrier, so every Agg read is complete.
    #pragma unroll
    for (int nt = 0; nt < 8; nt++) {
        int col = col0 + nt * 8;
        float b0 = bias[col], b1 = bias[col + 1];
        float2 o;
        o.x = acc[nt][0] + b0; o.y = acc[nt][1] + b1;
        o.x = o.x > 0.f ? o.x : 0.f;
        o.y = o.y > 0.f ? o.y : 0.f;
        *(float2*)&Agg[r0][col] = o;
        o.x = acc[nt][2] + b0; o.y = acc[nt][3] + b1;
        o.x = o.x > 0.f ? o.x : 0.f;
        o.y = o.y > 0.f ? o.y : 0.f;
        *(float2*)&Agg[r0 + 8][col] = o;
    }

    // -------- Phase C: GEMM2 h (K=128, from smem) @ B2 -> z1 | r1 ----------
    float acc2[8][4];
    #pragma unroll
    for (int t = 0; t < 8; t++) {
        acc2[t][0] = 0.f; acc2[t][1] = 0.f; acc2[t][2] = 0.f; acc2[t][3] = 0.f;
    }

    for (int kc = 0; kc < 128; kc += 16) {
        __syncthreads();   // first iter: fences h-stores; later: Bs consumed
        {
            float4 v = *(const float4*)&Agg[arow][kc + akp];
            uint32_t h0, l0, h1, l1;
            split2(v.x, v.y, h0, l0);
            split2(v.z, v.w, h1, l1);
            Ahu[acol] = h0; Ahu[acol + 1] = h1;
            Alu[acol] = l0; Alu[acol + 1] = l1;
        }
        {
            const uint4* s4h = (const uint4*)(g_B2h + kc * B2U);
            const uint4* s4l = (const uint4*)(g_B2l + kc * B2U);
            #pragma unroll
            for (int i = tid; i < 16 * B2U / 4; i += 256) {
                ((uint4*)Bsh)[i] = s4h[i];
                ((uint4*)Bsl)[i] = s4l[i];
            }
        }
        __syncthreads();

        uint32_t ah0, ah1, ah2, ah3, al0, al1, al2, al3;
        LDSM_X4(ah0, ah1, ah2, ah3, aAddrH);
        LDSM_X4(al0, al1, al2, al3, aAddrL);

        #pragma unroll
        for (int p = 0; p < 4; p++) {
            uint32_t bh0, bh1, bh2, bh3, bl0, bl1, bl2, bl3;
            LDSM_X4_T(bh0, bh1, bh2, bh3, bAddrH + p * 32);
            LDSM_X4_T(bl0, bl1, bl2, bl3, bAddrL + p * 32);
            MMA16816(acc2[2*p],   ah0, ah1, ah2, ah3, bh0, bh1);
            MMA16816(acc2[2*p],   ah0, ah1, ah2, ah3, bl0, bl1);
            MMA16816(acc2[2*p],   al0, al1, al2, al3, bh0, bh1);
            MMA16816(acc2[2*p+1], ah0, ah1, ah2, ah3, bh2, bh3);
            MMA16816(acc2[2*p+1], ah0, ah1, ah2, ah3, bl2, bl3);
            MMA16816(acc2[2*p+1], al0, al1, al2, al3, bh2, bh3);
        }
    }

    // -------- epilogue: z1 | r1 --------
    #pragma unroll
    for (int nt = 0; nt < 8; nt++) {
        int col = col0 + nt * 8;
        float* dst = (col < 64) ? g_z1 : g_r1;
        int c = col & 63;
        if (gm0 < M) {
            float2 o; o.x = acc2[nt][0]; o.y = acc2[nt][1];
            *(float2*)&dst[gm0 * 64 + c] = o;
        }
        if (gm1 < M) {
            float2 o; o.x = acc2[nt][2]; o.y = acc2[nt][3];
            *(float2*)&dst[gm1 * 64 + c] = o;
        }
    }
}

// ---------------- final: out = mean_agg(z1) + bl1 + r1 ---------------------
__global__ void k_out(const float* __restrict__ bias, float* __restrict__ out, int n) {
    int warp = (blockIdx.x * blockDim.x + threadIdx.x) >> 5;
    int lane = threadIdx.x & 31;
    if (warp >= n) return;
    int rs = g_rptr[warp], re = g_rptr[warp + 1];
    int d0 = lane * 2;
    float2 acc = make_float2(0.f, 0.f);
    int j = rs;
    for (; j + 4 <= re; j += 4) {
        int s0 = g_col[j], s1 = g_col[j + 1], s2 = g_col[j + 2], s3 = g_col[j + 3];
        float2 v0 = *(const float2*)&g_z1[s0 * 64 + d0];
        float2 v1 = *(const float2*)&g_z1[s1 * 64 + d0];
        float2 v2 = *(const float2*)&g_z1[s2 * 64 + d0];
        float2 v3 = *(const float2*)&g_z1[s3 * 64 + d0];
        acc.x += v0.x + v1.x + v2.x + v3.x;
        acc.y += v0.y + v1.y + v2.y + v3.y;
    }
    for (; j < re; j++) {
        int s = g_col[j];
        float2 v = *(const float2*)&g_z1[s * 64 + d0];
        acc.x += v.x; acc.y += v.y;
    }
    int deg = re - rs;
    float inv = 1.0f / (float)(deg > 1 ? deg : 1);
    float2 r = *(const float2*)&g_r1[warp * 64 + d0];
    float2 o;
    o.x = acc.x * inv + bias[d0]     + r.x;
    o.y = acc.y * inv + bias[d0 + 1] + r.y;
    *(float2*)&out[warp * 64 + d0] = o;
}

// ---------------- launch (kernel launches ONLY) ----------------------------
extern "C" void kernel_launch(void* const* d_in, const int* in_sizes, int n_in,
                              void* d_out, int out_size) {
    const float* x   = (const float*)d_in[0];
    const void*  ei  = d_in[1];
    const float* Wl0 = (const float*)d_in[2];
    const float* bl0 = (const float*)d_in[3];
    const float* Wr0 = (const float*)d_in[4];
    const float* Wl1 = (const float*)d_in[5];
    const float* bl1 = (const float*)d_in[6];
    const float* Wr1 = (const float*)d_in[7];
    float* out = (float*)d_out;

    int M = in_sizes[0] / 128;      // 100000
    int E = in_sizes[1] / 2;        // 1600000

    k_detect<<<1, 256>>>((const int*)ei);
    k_zero_cnt<<<(M + 255) / 256, 256>>>(M);
    k_hist<<<(E + 255) / 256, 256>>>(ei, E);
    k_scan_blocks<<<NB, SCAN_B>>>(M);
    k_scan_bsum<<<1, 128>>>(NB);
    k_add_off<<<NB, SCAN_B>>>(M, E);
    k_scatter<<<(E + 255) / 256, 256>>>(ei, E);
    k_pack<<<(256 * B1U + 255) / 256, 256>>>(Wl0, Wr0, Wl1, Wr1);

    int tiles = (M + 63) / 64;
    k_layer1<<<tiles, 256>>>(x, bl0, M);
    k_out<<<(M + 7) / 8, 256>>>(bl1, out, M);
}